// round 1
// baseline (speedup 1.0000x reference)
#include <cuda_runtime.h>
#include <cuda_bf16.h>

// BSplineActivation: y = sum_i B_i^3(clip(x,-1,1)) * c_i over a uniform
// 12-knot grid with 8 coefficients.
//
// Key transform: uniform knots => per knot-interval j (0..10), the spline is a
// single cubic polynomial in t = (xc - g_j)/h. We fold the 4 active uniform
// B-spline basis polynomials with the (zero-padded) coefficients into an
// 11-entry float4 table of cubic coefficients, computed once per block.
// Per element: clamp, 1 fma-class index calc, 1 LDS.128, 3 FMA (Horner).
// Memory-bound: 67 MB streamed.

#define THREADS 256

__global__ void __launch_bounds__(THREADS)
bspline_act_kernel(const float* __restrict__ x,
                   const float* __restrict__ grid,
                   const float* __restrict__ coef,
                   float* __restrict__ out,
                   int n)
{
    __shared__ float4 sP[11];
    __shared__ float  sG0, sInvH;

    const int tid = threadIdx.x;

    // Per-block prologue: build per-interval cubic coefficient table.
    if (tid < 11) {
        // Active reference bases for interval j are i = j-3 .. j (clamped to [0,8)).
        float c0, c1, c2, c3;
        {
            int i0 = tid - 3, i1 = tid - 2, i2 = tid - 1, i3 = tid;
            c0 = (i0 >= 0 && i0 < 8) ? __ldg(&coef[i0]) : 0.0f;
            c1 = (i1 >= 0 && i1 < 8) ? __ldg(&coef[i1]) : 0.0f;
            c2 = (i2 >= 0 && i2 < 8) ? __ldg(&coef[i2]) : 0.0f;
            c3 = (i3 >= 0 && i3 < 8) ? __ldg(&coef[i3]) : 0.0f;
        }
        // Uniform cubic B-spline bases in t:
        //  N0=(1-3t+3t^2-t^3)/6  N1=(4-6t^2+3t^3)/6
        //  N2=(1+3t+3t^2-3t^3)/6 N3=t^3/6
        float4 P;
        P.x = (c0 + 4.0f * c1 + c2) * (1.0f / 6.0f);
        P.y = (c2 - c0) * 0.5f;
        P.z = (c0 - 2.0f * c1 + c2) * 0.5f;
        P.w = (c3 - c0 + 3.0f * (c1 - c2)) * (1.0f / 6.0f);
        sP[tid] = P;
        if (tid == 0) {
            float g0  = __ldg(&grid[0]);
            float g11 = __ldg(&grid[11]);
            sG0   = g0;
            sInvH = 11.0f / (g11 - g0);
        }
    }
    __syncthreads();

    const float g0   = sG0;
    const float invh = sInvH;

    const int n4 = n >> 2;
    const float4* __restrict__ x4 = (const float4*)x;
    float4* __restrict__ o4 = (float4*)out;

    for (int idx = blockIdx.x * THREADS + tid; idx < n4;
         idx += gridDim.x * THREADS) {
        float4 v = x4[idx];
        float4 r;

        #pragma unroll
        for (int k = 0; k < 4; k++) {
            float xv = (k == 0) ? v.x : (k == 1) ? v.y : (k == 2) ? v.z : v.w;
            float xc = fminf(fmaxf(xv, -1.0f), 1.0f);
            float u  = (xc - g0) * invh;      // in ~(0.91, 10.09)
            int   j  = (int)u;                // trunc == floor (u > 0)
            j = min(max(j, 0), 10);           // fp safety clamp
            float t  = u - (float)j;
            float4 P = sP[j];
            float y  = fmaf(fmaf(fmaf(P.w, t, P.z), t, P.y), t, P.x);
            if (k == 0) r.x = y; else if (k == 1) r.y = y;
            else if (k == 2) r.z = y; else r.w = y;
        }
        o4[idx] = r;
    }

    // Tail for n not divisible by 4 (not hit for 2048x4096, kept for safety).
    const int rem = n & 3;
    if (rem && blockIdx.x == 0 && tid < rem) {
        int idx = (n4 << 2) + tid;
        float xc = fminf(fmaxf(x[idx], -1.0f), 1.0f);
        float u  = (xc - g0) * invh;
        int   j  = min(max((int)u, 0), 10);
        float t  = u - (float)j;
        float4 P = sP[j];
        out[idx] = fmaf(fmaf(fmaf(P.w, t, P.z), t, P.y), t, P.x);
    }
}

extern "C" void kernel_launch(void* const* d_in, const int* in_sizes, int n_in,
                              void* d_out, int out_size)
{
    const float* x    = (const float*)d_in[0];   // [2048*4096] fp32
    const float* grid = (const float*)d_in[1];   // [12] fp32
    const float* coef = (const float*)d_in[2];   // [8] fp32
    float* out = (float*)d_out;

    const int n  = in_sizes[0];
    const int n4 = (n + 3) >> 2;
    int blocks = (n4 + THREADS - 1) / THREADS;
    if (blocks > 16384) blocks = 16384;
    if (blocks < 1) blocks = 1;

    bspline_act_kernel<<<blocks, THREADS>>>(x, grid, coef, out, n);
}

// round 2
// speedup vs baseline: 1.2752x; 1.2752x over previous
#include <cuda_runtime.h>
#include <cuda_bf16.h>

// BSplineActivation: y = sum_i B_i^3(clip(x,-1,1)) * c_i, uniform 12-knot grid,
// 8 coefficients. Uniform knots => per interval j (0..10) the spline is one
// cubic in t = frac((xc-g0)/h). We fold bases+coefficients into an 11-entry
// cubic table, stored SoA (4 scalar arrays) so the divergent per-element
// gather is 4x conflict-free LDS.32 (11 words span 11 distinct banks).
// Each thread processes 4 float4 (16 elements) with front-batched loads
// (MLP=4) to hide memory + LDS latency.

#define THREADS 256
#define VPT 4   // float4 per thread

__global__ void __launch_bounds__(THREADS)
bspline_act_kernel(const float* __restrict__ x,
                   const float* __restrict__ grid,
                   const float* __restrict__ coef,
                   float* __restrict__ out,
                   int n4)
{
    // SoA table: each array of 11 floats covers 11 distinct smem banks
    // (arrays start 16 words apart) -> divergent LDS.32 is conflict-free.
    __shared__ float sP0[16], sP1[16], sP2[16], sP3[16];
    __shared__ float sG0, sInvH;

    const int tid = threadIdx.x;

    if (tid < 11) {
        int i0 = tid - 3, i1 = tid - 2, i2 = tid - 1, i3 = tid;
        float c0 = (i0 >= 0 && i0 < 8) ? __ldg(&coef[i0]) : 0.0f;
        float c1 = (i1 >= 0 && i1 < 8) ? __ldg(&coef[i1]) : 0.0f;
        float c2 = (i2 >= 0 && i2 < 8) ? __ldg(&coef[i2]) : 0.0f;
        float c3 = (i3 >= 0 && i3 < 8) ? __ldg(&coef[i3]) : 0.0f;
        // Uniform cubic B-spline basis polynomials in t, folded with coefs:
        sP0[tid] = (c0 + 4.0f * c1 + c2) * (1.0f / 6.0f);
        sP1[tid] = (c2 - c0) * 0.5f;
        sP2[tid] = (c0 - 2.0f * c1 + c2) * 0.5f;
        sP3[tid] = (c3 - c0 + 3.0f * (c1 - c2)) * (1.0f / 6.0f);
        if (tid == 0) {
            float g0  = __ldg(&grid[0]);
            float g11 = __ldg(&grid[11]);
            sG0   = g0;
            sInvH = 11.0f / (g11 - g0);
        }
    }
    __syncthreads();

    const float g0   = sG0;
    const float invh = sInvH;

    const float4* __restrict__ x4 = (const float4*)x;
    float4* __restrict__ o4 = (float4*)out;

    const int base = blockIdx.x * (THREADS * VPT) + tid;

    // Front-batched loads: 4 independent LDG.128 in flight per thread.
    float4 v[VPT];
    #pragma unroll
    for (int q = 0; q < VPT; q++) {
        int i = base + q * THREADS;
        if (i < n4) v[q] = x4[i];
    }

    float4 r[VPT];
    #pragma unroll
    for (int q = 0; q < VPT; q++) {
        #pragma unroll
        for (int k = 0; k < 4; k++) {
            float xv = (k == 0) ? v[q].x : (k == 1) ? v[q].y
                     : (k == 2) ? v[q].z : v[q].w;
            float xc = fminf(fmaxf(xv, -1.0f), 1.0f);
            float u  = (xc - g0) * invh;        // ~ (0.91, 10.09) > 0
            int   j  = (int)u;                  // trunc == floor
            j = min(max(j, 0), 10);
            float t  = u - (float)j;
            float p3 = sP3[j];
            float p2 = sP2[j];
            float p1 = sP1[j];
            float p0 = sP0[j];
            float y  = fmaf(fmaf(fmaf(p3, t, p2), t, p1), t, p0);
            if (k == 0) r[q].x = y; else if (k == 1) r[q].y = y;
            else if (k == 2) r[q].z = y; else r[q].w = y;
        }
    }

    #pragma unroll
    for (int q = 0; q < VPT; q++) {
        int i = base + q * THREADS;
        if (i < n4) o4[i] = r[q];
    }
}

// Scalar tail kernel for n % 4 != 0 (not hit for 2048x4096).
__global__ void bspline_tail_kernel(const float* __restrict__ x,
                                    const float* __restrict__ grid,
                                    const float* __restrict__ coef,
                                    float* __restrict__ out,
                                    int start, int n)
{
    int idx = start + threadIdx.x;
    if (idx >= n) return;
    float g0  = grid[0];
    float invh = 11.0f / (grid[11] - g0);
    float xc = fminf(fmaxf(x[idx], -1.0f), 1.0f);
    float u  = (xc - g0) * invh;
    int   j  = min(max((int)u, 0), 10);
    float t  = u - (float)j;
    int i0 = j - 3, i1 = j - 2, i2 = j - 1, i3 = j;
    float c0 = (i0 >= 0 && i0 < 8) ? coef[i0] : 0.0f;
    float c1 = (i1 >= 0 && i1 < 8) ? coef[i1] : 0.0f;
    float c2 = (i2 >= 0 && i2 < 8) ? coef[i2] : 0.0f;
    float c3 = (i3 >= 0 && i3 < 8) ? coef[i3] : 0.0f;
    float p0 = (c0 + 4.0f * c1 + c2) * (1.0f / 6.0f);
    float p1 = (c2 - c0) * 0.5f;
    float p2 = (c0 - 2.0f * c1 + c2) * 0.5f;
    float p3 = (c3 - c0 + 3.0f * (c1 - c2)) * (1.0f / 6.0f);
    out[idx] = fmaf(fmaf(fmaf(p3, t, p2), t, p1), t, p0);
}

extern "C" void kernel_launch(void* const* d_in, const int* in_sizes, int n_in,
                              void* d_out, int out_size)
{
    const float* x    = (const float*)d_in[0];   // [2048*4096] fp32
    const float* grid = (const float*)d_in[1];   // [12] fp32
    const float* coef = (const float*)d_in[2];   // [8] fp32
    float* out = (float*)d_out;

    const int n  = in_sizes[0];
    const int n4 = n >> 2;

    int per_block = THREADS * VPT;
    int blocks = (n4 + per_block - 1) / per_block;
    if (blocks < 1) blocks = 1;

    bspline_act_kernel<<<blocks, THREADS>>>(x, grid, coef, out, n4);

    const int rem = n & 3;
    if (rem) {
        bspline_tail_kernel<<<1, 4>>>(x, grid, coef, out, n4 << 2, n);
    }
}

// round 3
// speedup vs baseline: 1.3008x; 1.0201x over previous
#include <cuda_runtime.h>
#include <cuda_bf16.h>

// BSplineActivation: y = sum_i B_i^3(clip(x,-1,1)) * c_i, uniform 12-knot
// grid, 8 coefficients. Uniform knots => per interval j (0..10) the spline is
// one cubic in t. Bases+coefficients folded into an 11-entry cubic table,
// stored as two float2 arrays so the per-element gather is 2x conflict-free
// LDS.64 (11 float2 = 22 words < 32 banks). 16 elements/thread with
// front-batched float4 loads (MLP=4). Issue-bound: ~12 instr/element.

#define THREADS 256
#define VPT 4   // float4 per thread

__global__ void __launch_bounds__(THREADS, 4)
bspline_act_kernel(const float* __restrict__ x,
                   const float* __restrict__ grid,
                   const float* __restrict__ coef,
                   float* __restrict__ out,
                   int n4)
{
    // Paired tables: sA[j] = {P0,P1}, sB[j] = {P2,P3}.
    __shared__ float2 sA[16];
    __shared__ float2 sB[16];
    __shared__ float  sInvH, sC;   // u = x*invh + c

    const int tid = threadIdx.x;

    if (tid < 16) {
        float c0 = 0.f, c1 = 0.f, c2 = 0.f, c3 = 0.f;
        if (tid < 11) {
            int i0 = tid - 3, i1 = tid - 2, i2 = tid - 1, i3 = tid;
            c0 = (i0 >= 0 && i0 < 8) ? __ldg(&coef[i0]) : 0.0f;
            c1 = (i1 >= 0 && i1 < 8) ? __ldg(&coef[i1]) : 0.0f;
            c2 = (i2 >= 0 && i2 < 8) ? __ldg(&coef[i2]) : 0.0f;
            c3 = (i3 >= 0 && i3 < 8) ? __ldg(&coef[i3]) : 0.0f;
        }
        // Uniform cubic B-spline basis polynomials in t, folded with coefs.
        float2 A, B;
        A.x = (c0 + 4.0f * c1 + c2) * (1.0f / 6.0f);          // P0
        A.y = (c2 - c0) * 0.5f;                               // P1
        B.x = (c0 - 2.0f * c1 + c2) * 0.5f;                   // P2
        B.y = (c3 - c0 + 3.0f * (c1 - c2)) * (1.0f / 6.0f);   // P3
        sA[tid] = A;
        sB[tid] = B;
        if (tid == 0) {
            float g0   = __ldg(&grid[0]);
            float g11  = __ldg(&grid[11]);
            float invh = 11.0f / (g11 - g0);
            sInvH = invh;
            sC    = -g0 * invh;
        }
    }
    __syncthreads();

    const float invh = sInvH;
    const float cadd = sC;

    const float4* __restrict__ x4 = (const float4*)x;
    float4* __restrict__ o4 = (float4*)out;

    const int base = blockIdx.x * (THREADS * VPT) + tid;

    float4 v[VPT];
    #pragma unroll
    for (int q = 0; q < VPT; q++) {
        int i = base + q * THREADS;
        if (i < n4) v[q] = x4[i];
    }

    float4 r[VPT];
    #pragma unroll
    for (int q = 0; q < VPT; q++) {
        #pragma unroll
        for (int k = 0; k < 4; k++) {
            float xv = (k == 0) ? v[q].x : (k == 1) ? v[q].y
                     : (k == 2) ? v[q].z : v[q].w;
            float xc = fminf(fmaxf(xv, -1.0f), 1.0f);
            float u  = fmaf(xc, invh, cadd);    // in (0.91, 10.09): no clamp
            int   j  = (int)u;                  // trunc == floor (u > 0)
            float t  = u - (float)j;
            float2 A = sA[j];
            float2 B = sB[j];
            float y  = fmaf(fmaf(fmaf(B.y, t, B.x), t, A.y), t, A.x);
            if (k == 0) r[q].x = y; else if (k == 1) r[q].y = y;
            else if (k == 2) r[q].z = y; else r[q].w = y;
        }
    }

    #pragma unroll
    for (int q = 0; q < VPT; q++) {
        int i = base + q * THREADS;
        if (i < n4) o4[i] = r[q];
    }
}

// Scalar tail kernel for n % 4 != 0 (not hit for 2048x4096).
__global__ void bspline_tail_kernel(const float* __restrict__ x,
                                    const float* __restrict__ grid,
                                    const float* __restrict__ coef,
                                    float* __restrict__ out,
                                    int start, int n)
{
    int idx = start + threadIdx.x;
    if (idx >= n) return;
    float g0  = grid[0];
    float invh = 11.0f / (grid[11] - g0);
    float xc = fminf(fmaxf(x[idx], -1.0f), 1.0f);
    float u  = (xc - g0) * invh;
    int   j  = min(max((int)u, 0), 10);
    float t  = u - (float)j;
    int i0 = j - 3, i1 = j - 2, i2 = j - 1, i3 = j;
    float c0 = (i0 >= 0 && i0 < 8) ? coef[i0] : 0.0f;
    float c1 = (i1 >= 0 && i1 < 8) ? coef[i1] : 0.0f;
    float c2 = (i2 >= 0 && i2 < 8) ? coef[i2] : 0.0f;
    float c3 = (i3 >= 0 && i3 < 8) ? coef[i3] : 0.0f;
    float p0 = (c0 + 4.0f * c1 + c2) * (1.0f / 6.0f);
    float p1 = (c2 - c0) * 0.5f;
    float p2 = (c0 - 2.0f * c1 + c2) * 0.5f;
    float p3 = (c3 - c0 + 3.0f * (c1 - c2)) * (1.0f / 6.0f);
    out[idx] = fmaf(fmaf(fmaf(p3, t, p2), t, p1), t, p0);
}

extern "C" void kernel_launch(void* const* d_in, const int* in_sizes, int n_in,
                              void* d_out, int out_size)
{
    const float* x    = (const float*)d_in[0];   // [2048*4096] fp32
    const float* grid = (const float*)d_in[1];   // [12] fp32
    const float* coef = (const float*)d_in[2];   // [8] fp32
    float* out = (float*)d_out;

    const int n  = in_sizes[0];
    const int n4 = n >> 2;

    int per_block = THREADS * VPT;
    int blocks = (n4 + per_block - 1) / per_block;
    if (blocks < 1) blocks = 1;

    bspline_act_kernel<<<blocks, THREADS>>>(x, grid, coef, out, n4);

    const int rem = n & 3;
    if (rem) {
        bspline_tail_kernel<<<1, 4>>>(x, grid, coef, out, n4 << 2, n);
    }
}